// round 8
// baseline (speedup 1.0000x reference)
#include <cuda_runtime.h>
#include <cuda_bf16.h>

// DensityEstimator: per-channel 1->3->3->3->1 MLP, p = cdf(x+.5) - cdf(x-.5)
// R8: R6 body unchanged (2 elems/thread = 4 tanh chains, register weights,
// bm0 eliminated). Only knob changed: 51-reg cap -> 5 blocks/SM = 40 warps,
// to push the MUFU pipe (20 tanh/elem x rt8 = 82% busy at R6's 23 warps)
// toward saturation. ~9 reg slots spill to local; lane-coalesced LDL at
// ~14 cyc/elem-warp vs the 160-cyc MUFU budget.
// Grid 735: 735*256 = 188160 = 192*980 -> channel fixed per thread;
// 4.97 blocks/SM -> single wave.

#define NCH  192
#define NBLK 735
#define NTHR 256

__device__ __forceinline__ float tanha(float x) {
    float r; asm("tanh.approx.f32 %0, %1;" : "=f"(r) : "f"(x)); return r;
}
__device__ __forceinline__ float softplus_acc(float h) {
    return (h > 15.0f) ? h : log1pf(expf(h));
}

struct W {
    float sh0[3], sh1[9], sh2[9], sh3[3];
    float ta0[3], ta1[3], ta2[3];
    float bp0[3], bb1[3], bb2[3], bb3;
};

// One element, both cdf branches. tm = tp - sh0[j] replaces the bm0 weights.
__device__ __forceinline__ float de_one(float xv, const W& w) {
    float yp[3], ym[3];
#pragma unroll
    for (int j = 0; j < 3; j++) {
        float tp = fmaf(xv, w.sh0[j], w.bp0[j]);   // at x + 0.5
        float tm = tp - w.sh0[j];                  // at x - 0.5 (exact)
        yp[j] = fmaf(w.ta0[j], tanha(tp), tp);
        ym[j] = fmaf(w.ta0[j], tanha(tm), tm);
    }
    float zp[3], zm[3];
#pragma unroll
    for (int p = 0; p < 3; p++) {
        float sp = w.bb1[p], sm = w.bb1[p];
#pragma unroll
        for (int j = 0; j < 3; j++) {
            sp = fmaf(yp[j], w.sh1[j*3 + p], sp);
            sm = fmaf(ym[j], w.sh1[j*3 + p], sm);
        }
        zp[p] = fmaf(w.ta1[p], tanha(sp), sp);
        zm[p] = fmaf(w.ta1[p], tanha(sm), sm);
    }
#pragma unroll
    for (int p = 0; p < 3; p++) {
        float sp = w.bb2[p], sm = w.bb2[p];
#pragma unroll
        for (int j = 0; j < 3; j++) {
            sp = fmaf(zp[j], w.sh2[j*3 + p], sp);
            sm = fmaf(zm[j], w.sh2[j*3 + p], sm);
        }
        yp[p] = fmaf(w.ta2[p], tanha(sp), sp);
        ym[p] = fmaf(w.ta2[p], tanha(sm), sm);
    }
    float fp = w.bb3, fm = w.bb3;
#pragma unroll
    for (int j = 0; j < 3; j++) {
        fp = fmaf(yp[j], w.sh3[j], fp);
        fm = fmaf(ym[j], w.sh3[j], fm);
    }
    return 0.5f * (tanha(fp) - tanha(fm));
}

__global__ void __launch_bounds__(NTHR, 5) de_kernel(
    const float* __restrict__ x,
    const float* __restrict__ a0, const float* __restrict__ a1, const float* __restrict__ a2,
    const float* __restrict__ b0, const float* __restrict__ b1, const float* __restrict__ b2,
    const float* __restrict__ b3,
    const float* __restrict__ H0, const float* __restrict__ H1, const float* __restrict__ H2,
    const float* __restrict__ H3,
    float* __restrict__ out, int n)
{
    const int T  = gridDim.x * blockDim.x;          // 188160, multiple of 192
    const int i0 = blockIdx.x * blockDim.x + threadIdx.x;
    const int c  = i0 % NCH;                        // fixed channel (T % 192 == 0)

    // One-time per-thread weight transform (40 values; a few spill under the
    // 51-reg cap -- intended tradeoff for 5 blocks/SM).
    W w;
#pragma unroll
    for (int j = 0; j < 3; j++) {
        w.sh0[j] = softplus_acc(__ldg(&H0[c*3 + j]));          // H0: (C,1,3)
        w.sh3[j] = 0.5f * softplus_acc(__ldg(&H3[c*3 + j]));   // H3: (C,3,1), 1/2 folded
        w.ta0[j] = tanhf(__ldg(&a0[c*3 + j]));
        w.ta1[j] = tanhf(__ldg(&a1[c*3 + j]));
        w.ta2[j] = tanhf(__ldg(&a2[c*3 + j]));
        w.bp0[j] = fmaf(0.5f, w.sh0[j], __ldg(&b0[c*3 + j]));  // x+0.5 folded
        w.bb1[j] = __ldg(&b1[c*3 + j]);
        w.bb2[j] = __ldg(&b2[c*3 + j]);
    }
#pragma unroll
    for (int j = 0; j < 9; j++) {
        w.sh1[j] = softplus_acc(__ldg(&H1[c*9 + j]));          // H1: (C,3,3) [i*3+p]
        w.sh2[j] = softplus_acc(__ldg(&H2[c*9 + j]));
    }
    w.bb3 = 0.5f * __ldg(&b3[c]);                              // 1/2 folded

    // Two elements per iteration; i and i+T share the channel.
    for (int i = i0; i < n; i += 2 * T) {
        const int  i2  = i + T;
        const bool ok2 = i2 < n;
        float xa = x[i];
        float xb = x[ok2 ? i2 : i];
        float ra = de_one(xa, w);
        float rb = de_one(xb, w);
        out[i] = ra;
        if (ok2) out[i2] = rb;
    }
}

extern "C" void kernel_launch(void* const* d_in, const int* in_sizes, int n_in,
                              void* d_out, int out_size)
{
    const float* x  = (const float*)d_in[0];
    const float* a0 = (const float*)d_in[1];
    const float* a1 = (const float*)d_in[2];
    const float* a2 = (const float*)d_in[3];
    const float* b0 = (const float*)d_in[4];
    const float* b1 = (const float*)d_in[5];
    const float* b2 = (const float*)d_in[6];
    const float* b3 = (const float*)d_in[7];
    const float* H0 = (const float*)d_in[8];
    const float* H1 = (const float*)d_in[9];
    const float* H2 = (const float*)d_in[10];
    const float* H3 = (const float*)d_in[11];
    float* out = (float*)d_out;
    int n = in_sizes[0];   // 65536 * 192

    de_kernel<<<NBLK, NTHR>>>(x, a0, a1, a2, b0, b1, b2, b3,
                              H0, H1, H2, H3, out, n);
}

// round 9
// speedup vs baseline: 1.0479x; 1.0479x over previous
#include <cuda_runtime.h>
#include <cuda_bf16.h>

// DensityEstimator: per-channel 1->3->3->3->1 MLP, p = cdf(x+.5) - cdf(x-.5)
// R9: occupancy is the lever (time*warps ~ const across R3/R4/R6).
// -> 5 blocks/SM (51-reg cap) = 40 resident warps, 1 elem/thread.
// R8's failure (ptxas rematerializing spilled weights as in-loop LDGs, L2=31%)
// is fixed by (a) a separate weight-transform kernel writing a __device__
// scratch (no softplus chain left to remat) and (b) identity-__shfl_sync
// "laundering" of every weight so remat is impossible -> pressure becomes
// cheap lane-coalesced STL/LDL only.

#define NCH  192
#define NBLK 735          // 735*256 = 188160 = 192*980; 4.97 blocks/SM
#define NTHR 256
#define NW   43

// Transformed weights, [k][c] layout (c fastest -> coalesced main-kernel loads).
__device__ float g_wt[NW * NCH];

__device__ __forceinline__ float tanha(float x) {
    float r; asm("tanh.approx.f32 %0, %1;" : "=f"(r) : "f"(x)); return r;
}
__device__ __forceinline__ float softplus_acc(float h) {
    return (h > 15.0f) ? h : log1pf(expf(h));
}

// ---- Kernel 1: one-time weight transform (192 threads, one channel each) ----
__global__ void wt_kernel(
    const float* __restrict__ a0, const float* __restrict__ a1, const float* __restrict__ a2,
    const float* __restrict__ b0, const float* __restrict__ b1, const float* __restrict__ b2,
    const float* __restrict__ b3,
    const float* __restrict__ H0, const float* __restrict__ H1, const float* __restrict__ H2,
    const float* __restrict__ H3)
{
    const int c = threadIdx.x;
    if (c >= NCH) return;
#pragma unroll
    for (int j = 0; j < 3; j++) {
        float s0 = softplus_acc(H0[c*3 + j]);                  // H0: (C,1,3)
        g_wt[(0 + j)*NCH + c]  = s0;                           // sh0
        g_wt[(3 + j)*NCH + c]  = fmaf(0.5f, s0, b0[c*3 + j]);  // bp0 (x+0.5 folded)
        g_wt[(6 + j)*NCH + c]  = tanhf(a0[c*3 + j]);           // ta0
        g_wt[(18 + j)*NCH + c] = tanhf(a1[c*3 + j]);           // ta1
        g_wt[(21 + j)*NCH + c] = b1[c*3 + j];                  // bb1
        g_wt[(33 + j)*NCH + c] = tanhf(a2[c*3 + j]);           // ta2
        g_wt[(36 + j)*NCH + c] = b2[c*3 + j];                  // bb2
        g_wt[(39 + j)*NCH + c] = 0.5f * softplus_acc(H3[c*3 + j]); // sh3, 1/2 folded
    }
#pragma unroll
    for (int j = 0; j < 9; j++) {
        g_wt[(9 + j)*NCH + c]  = softplus_acc(H1[c*9 + j]);    // sh1 [i*3+p]
        g_wt[(24 + j)*NCH + c] = softplus_acc(H2[c*9 + j]);    // sh2 [i*3+p]
    }
    g_wt[42*NCH + c] = 0.5f * b3[c];                           // bb3, 1/2 folded
}

// ---- Kernel 2: main evaluation, 1 elem/thread, 40 warps/SM ----
__global__ void __launch_bounds__(NTHR, 5) de_kernel(
    const float* __restrict__ x, float* __restrict__ out, int n)
{
    const int T  = gridDim.x * blockDim.x;          // 188160, multiple of 192
    const int i0 = blockIdx.x * blockDim.x + threadIdx.x;
    const int c  = i0 % NCH;                        // fixed channel (T % 192 == 0)

    // Coalesced weight fetch + shfl launder (identity shfl: remat-proof).
    float w[NW];
    const float* wp = g_wt + c;
#pragma unroll
    for (int k = 0; k < NW; k++) {
        float v = wp[k * NCH];
        w[k] = __shfl_sync(0xffffffffu, v, threadIdx.x & 31);
    }
    const float* sh0 = w;        const float* bp0 = w + 3;
    const float* ta0 = w + 6;    const float* sh1 = w + 9;
    const float* ta1 = w + 18;   const float* bb1 = w + 21;
    const float* sh2 = w + 24;   const float* ta2 = w + 33;
    const float* bb2 = w + 36;   const float* sh3 = w + 39;
    const float  bb3 = w[42];

    for (int i = i0; i < n; i += T) {
        float xv = x[i];

        // Layer 0: 1 -> 3 (m-branch arg = p-branch arg - sh0, exact)
        float yp[3], ym[3];
#pragma unroll
        for (int j = 0; j < 3; j++) {
            float tp = fmaf(xv, sh0[j], bp0[j]);
            float tm = tp - sh0[j];
            yp[j] = fmaf(ta0[j], tanha(tp), tp);
            ym[j] = fmaf(ta0[j], tanha(tm), tm);
        }
        // Layer 1: 3 -> 3
        float zp[3], zm[3];
#pragma unroll
        for (int p = 0; p < 3; p++) {
            float sp = bb1[p], sm = bb1[p];
#pragma unroll
            for (int j = 0; j < 3; j++) {
                sp = fmaf(yp[j], sh1[j*3 + p], sp);
                sm = fmaf(ym[j], sh1[j*3 + p], sm);
            }
            zp[p] = fmaf(ta1[p], tanha(sp), sp);
            zm[p] = fmaf(ta1[p], tanha(sm), sm);
        }
        // Layer 2: 3 -> 3
#pragma unroll
        for (int p = 0; p < 3; p++) {
            float sp = bb2[p], sm = bb2[p];
#pragma unroll
            for (int j = 0; j < 3; j++) {
                sp = fmaf(zp[j], sh2[j*3 + p], sp);
                sm = fmaf(zm[j], sh2[j*3 + p], sm);
            }
            yp[p] = fmaf(ta2[p], tanha(sp), sp);
            ym[p] = fmaf(ta2[p], tanha(sm), sm);
        }
        // Layer 3: 3 -> 1 (1/2 folded) + tanh-form sigmoid difference
        float fp = bb3, fm = bb3;
#pragma unroll
        for (int j = 0; j < 3; j++) {
            fp = fmaf(yp[j], sh3[j], fp);
            fm = fmaf(ym[j], sh3[j], fm);
        }
        out[i] = 0.5f * (tanha(fp) - tanha(fm));
    }
}

extern "C" void kernel_launch(void* const* d_in, const int* in_sizes, int n_in,
                              void* d_out, int out_size)
{
    const float* x  = (const float*)d_in[0];
    const float* a0 = (const float*)d_in[1];
    const float* a1 = (const float*)d_in[2];
    const float* a2 = (const float*)d_in[3];
    const float* b0 = (const float*)d_in[4];
    const float* b1 = (const float*)d_in[5];
    const float* b2 = (const float*)d_in[6];
    const float* b3 = (const float*)d_in[7];
    const float* H0 = (const float*)d_in[8];
    const float* H1 = (const float*)d_in[9];
    const float* H2 = (const float*)d_in[10];
    const float* H3 = (const float*)d_in[11];
    float* out = (float*)d_out;
    int n = in_sizes[0];   // 65536 * 192

    wt_kernel<<<1, NCH>>>(a0, a1, a2, b0, b1, b2, b3, H0, H1, H2, H3);
    de_kernel<<<NBLK, NTHR>>>(x, out, n);
}

// round 10
// speedup vs baseline: 1.2308x; 1.1745x over previous
#include <cuda_runtime.h>
#include <cuda_bf16.h>

// DensityEstimator: per-channel 1->3->3->3->1 MLP, p = cdf(x+.5) - cdf(x-.5)
// R10: R6's proven optimum (2 elems/thread = 4 tanh chains, register weights,
// 64-reg cap, 4 blocks/SM, grid 591) with the expensive per-thread weight
// transform (43 scattered LDG + ~40 serial libm transcendentals) hoisted into
// a fully data-parallel kernel (one thread per transformed weight). The main
// kernel preamble is 43 coalesced LDGs ([k][c] layout, lane-consecutive c),
// shfl-laundered so ptxas cannot rematerialize them into the loop.

#define NCH  192
#define NBLK 591          // 591*256 = 151296 = 192*788; ~3.99 blocks/SM
#define NTHR 256
#define NW   43

__device__ float g_wt[NW * NCH];   // transformed weights, [k][c]

__device__ __forceinline__ float tanha(float x) {
    float r; asm("tanh.approx.f32 %0, %1;" : "=f"(r) : "f"(x)); return r;
}
__device__ __forceinline__ float softplus_acc(float h) {
    return (h > 15.0f) ? h : log1pf(expf(h));
}

// ---- Kernel 1: data-parallel weight transform, one thread per weight ----
// k: 0-2 sh0 | 3-5 bp0 | 6-8 ta0 | 9-17 sh1 | 18-20 ta1 | 21-23 bb1
//    24-32 sh2 | 33-35 ta2 | 36-38 bb2 | 39-41 sh3(1/2) | 42 bb3(1/2)
__global__ void wt_kernel(
    const float* __restrict__ a0, const float* __restrict__ a1, const float* __restrict__ a2,
    const float* __restrict__ b0, const float* __restrict__ b1, const float* __restrict__ b2,
    const float* __restrict__ b3,
    const float* __restrict__ H0, const float* __restrict__ H1, const float* __restrict__ H2,
    const float* __restrict__ H3)
{
    int t = blockIdx.x * blockDim.x + threadIdx.x;
    if (t >= NW * NCH) return;
    int k = t / NCH;
    int c = t % NCH;
    float v;
    if      (k <  3) v = softplus_acc(H0[c*3 + k]);
    else if (k <  6) { int j = k - 3;
                       v = fmaf(0.5f, softplus_acc(H0[c*3 + j]), b0[c*3 + j]); }
    else if (k <  9) v = tanhf(a0[c*3 + (k - 6)]);
    else if (k < 18) v = softplus_acc(H1[c*9 + (k - 9)]);
    else if (k < 21) v = tanhf(a1[c*3 + (k - 18)]);
    else if (k < 24) v = b1[c*3 + (k - 21)];
    else if (k < 33) v = softplus_acc(H2[c*9 + (k - 24)]);
    else if (k < 36) v = tanhf(a2[c*3 + (k - 33)]);
    else if (k < 39) v = b2[c*3 + (k - 36)];
    else if (k < 42) v = 0.5f * softplus_acc(H3[c*3 + (k - 39)]);
    else             v = 0.5f * b3[c];
    g_wt[k * NCH + c] = v;
}

// ---- One element, both cdf branches (tm = tp - sh0[j], exact) ----
struct W {
    float sh0[3], bp0[3], ta0[3], sh1[9], ta1[3], bb1[3];
    float sh2[9], ta2[3], bb2[3], sh3[3], bb3;
};

__device__ __forceinline__ float de_one(float xv, const W& w) {
    float yp[3], ym[3];
#pragma unroll
    for (int j = 0; j < 3; j++) {
        float tp = fmaf(xv, w.sh0[j], w.bp0[j]);   // at x + 0.5
        float tm = tp - w.sh0[j];                  // at x - 0.5
        yp[j] = fmaf(w.ta0[j], tanha(tp), tp);
        ym[j] = fmaf(w.ta0[j], tanha(tm), tm);
    }
    float zp[3], zm[3];
#pragma unroll
    for (int p = 0; p < 3; p++) {
        float sp = w.bb1[p], sm = w.bb1[p];
#pragma unroll
        for (int j = 0; j < 3; j++) {
            sp = fmaf(yp[j], w.sh1[j*3 + p], sp);
            sm = fmaf(ym[j], w.sh1[j*3 + p], sm);
        }
        zp[p] = fmaf(w.ta1[p], tanha(sp), sp);
        zm[p] = fmaf(w.ta1[p], tanha(sm), sm);
    }
#pragma unroll
    for (int p = 0; p < 3; p++) {
        float sp = w.bb2[p], sm = w.bb2[p];
#pragma unroll
        for (int j = 0; j < 3; j++) {
            sp = fmaf(zp[j], w.sh2[j*3 + p], sp);
            sm = fmaf(zm[j], w.sh2[j*3 + p], sm);
        }
        yp[p] = fmaf(w.ta2[p], tanha(sp), sp);
        ym[p] = fmaf(w.ta2[p], tanha(sm), sm);
    }
    float fp = w.bb3, fm = w.bb3;
#pragma unroll
    for (int j = 0; j < 3; j++) {
        fp = fmaf(yp[j], w.sh3[j], fp);
        fm = fmaf(ym[j], w.sh3[j], fm);
    }
    return 0.5f * (tanha(fp) - tanha(fm));
}

// ---- Kernel 2: main evaluation (R6 config) ----
__global__ void __launch_bounds__(NTHR, 4) de_kernel(
    const float* __restrict__ x, float* __restrict__ out, int n)
{
    const int T  = gridDim.x * blockDim.x;          // 151296, multiple of 192
    const int i0 = blockIdx.x * blockDim.x + threadIdx.x;
    const int c  = i0 % NCH;                        // fixed channel

    // 43 coalesced loads (lane-consecutive c), laundered via identity shfl.
    W w;
    float* wf = (float*)&w;
#pragma unroll
    for (int k = 0; k < NW; k++) {
        float v = g_wt[k * NCH + c];
        wf[k] = __shfl_sync(0xffffffffu, v, threadIdx.x & 31);
    }

    for (int i = i0; i < n; i += 2 * T) {
        const int  i2  = i + T;                     // same channel
        const bool ok2 = i2 < n;
        float xa = x[i];
        float xb = x[ok2 ? i2 : i];
        float ra = de_one(xa, w);
        float rb = de_one(xb, w);
        out[i] = ra;
        if (ok2) out[i2] = rb;
    }
}

extern "C" void kernel_launch(void* const* d_in, const int* in_sizes, int n_in,
                              void* d_out, int out_size)
{
    const float* x  = (const float*)d_in[0];
    const float* a0 = (const float*)d_in[1];
    const float* a1 = (const float*)d_in[2];
    const float* a2 = (const float*)d_in[3];
    const float* b0 = (const float*)d_in[4];
    const float* b1 = (const float*)d_in[5];
    const float* b2 = (const float*)d_in[6];
    const float* b3 = (const float*)d_in[7];
    const float* H0 = (const float*)d_in[8];
    const float* H1 = (const float*)d_in[9];
    const float* H2 = (const float*)d_in[10];
    const float* H3 = (const float*)d_in[11];
    float* out = (float*)d_out;
    int n = in_sizes[0];   // 65536 * 192

    wt_kernel<<<(NW * NCH + NTHR - 1) / NTHR, NTHR>>>(
        a0, a1, a2, b0, b1, b2, b3, H0, H1, H2, H3);
    de_kernel<<<NBLK, NTHR>>>(x, out, n);
}